// round 17
// baseline (speedup 1.0000x reference)
#include <cuda_runtime.h>
#include <cuda_bf16.h>
#include <cuda_fp16.h>
#include <cstdint>

#define N_NODES 100000
#define N_EDGES 1600000
#define IN_F 128
#define OUT_F 32
#define HEADS 2
#define NHF 64  // HEADS*OUT_F
#define SCAN_BLK 1024
#define N_SCAN_BLKS ((N_NODES + SCAN_BLK - 1) / SCAN_BLK)  // 98
#define GEMM_TILES ((N_NODES + 63) / 64)                    // 1563 (64-row tiles)
#define GEMM_GRID 592                                       // 148 SMs x 4 blocks

// ---- scratch (device globals; zero-initialized at module load) ----
__device__ __half g_feat_h[N_NODES * NHF];  // fp16 feat for the agg gathers
__device__ __half g_wt_h[72 * IN_F];        // B^T fp16: [n][k]; rows 64-67 = wl/wr folds
__device__ float g_el[N_NODES * HEADS];
__device__ float g_er[N_NODES * HEADS];
__device__ float g_a[N_NODES];
__device__ float g_b[N_NODES];
__device__ float g_vfold[NHF];
__device__ float g_cfold;
// CSR-by-dst scratch. INVARIANT: g_deg all-zero at entry (zero-init at load;
// k_scan3 re-zeroes each run). g_ticket reset by k_scan1's last block.
__device__ int g_deg[N_NODES];
__device__ int g_cur[N_NODES];
__device__ int g_off[N_NODES + 1];
__device__ int g_srcs[N_EDGES];
__device__ int g_blksum[N_SCAN_BLKS];
__device__ int g_ticket;

// ---- hist (4 edges/thread) + block 0: MLP fold, W transpose+fold to fp16 ----
__global__ void k_hist(const int* __restrict__ dst,
                       const float* __restrict__ W,
                       const float* __restrict__ attn_l, const float* __restrict__ attn_r,
                       const float* __restrict__ W1, const float* __restrict__ b1,
                       const float* __restrict__ W2, const float* __restrict__ b2) {
    const int t = threadIdx.x;
    if (blockIdx.x == 0) {
        if (t < NHF) {
            float v = 0.f;
            #pragma unroll
            for (int j = 0; j < OUT_F; ++j) v += W1[t * OUT_F + j] * W2[j];
            g_vfold[t] = v;
        }
        if (t == 0) {
            float c = b2[0];
            for (int j = 0; j < OUT_F; ++j) c += b1[j] * W2[j];
            g_cfold = c;
        }
        // W^T (fp16): rows 0-63 = W[k][n] transposed
        for (int i = t; i < IN_F * NHF; i += 256) {
            int k = i >> 6, n = i & 63;
            g_wt_h[n * IN_F + k] = __float2half(W[i]);
        }
        // rows 64-67 = W@attn_l (h0,h1), W@attn_r (h0,h1); rows 68-71 = 0
        for (int i = t; i < IN_F * 8; i += 256) {
            int k = i & 127, nx = i >> 7;  // nx 0..7
            float v = 0.f;
            if (nx < 4) {
                const float* av = (nx & 2) ? attn_r : attn_l;
                int h = nx & 1;
                for (int f = 0; f < 32; ++f)
                    v += W[k * 64 + h * 32 + f] * av[h * 32 + f];
            }
            g_wt_h[(64 + nx) * IN_F + k] = __float2half(v);
        }
    }
    int i = blockIdx.x * blockDim.x + t;
    if (i * 4 >= N_EDGES) return;
    int4 d = *(const int4*)&dst[i * 4];
    atomicAdd(&g_deg[d.x], 1);
    atomicAdd(&g_deg[d.y], 1);
    atomicAdd(&g_deg[d.z], 1);
    atomicAdd(&g_deg[d.w], 1);
}

// ---- scan phase 1+2 fused: per-block sums; last block scans the 98 sums ----
__global__ void k_scan1() {
    __shared__ int s[SCAN_BLK];
    __shared__ int is_last;
    int i = blockIdx.x * SCAN_BLK + threadIdx.x;
    s[threadIdx.x] = (i < N_NODES) ? g_deg[i] : 0;
    __syncthreads();
    #pragma unroll
    for (int off = SCAN_BLK / 2; off > 0; off >>= 1) {
        if (threadIdx.x < off) s[threadIdx.x] += s[threadIdx.x + off];
        __syncthreads();
    }
    if (threadIdx.x == 0) {
        g_blksum[blockIdx.x] = s[0];
        __threadfence();
        int t = atomicAdd(&g_ticket, 1);
        is_last = (t == gridDim.x - 1);
    }
    __syncthreads();
    if (!is_last) return;
    __shared__ int s2[128];
    int t = threadIdx.x;
    if (t < 128) {
        int v = (t < N_SCAN_BLKS) ? g_blksum[t] : 0;
        s2[t] = v;
        __syncthreads();
        #pragma unroll
        for (int off = 1; off < 128; off <<= 1) {
            int u = (t >= off) ? s2[t - off] : 0;
            __syncthreads();
            s2[t] += u;
            __syncthreads();
        }
        if (t < N_SCAN_BLKS) g_blksum[t] = s2[t] - v;  // exclusive prefix
        if (t == 127) g_off[N_NODES] = s2[127];
        if (t == 0) g_ticket = 0;                      // restore invariant
    } else {
        __syncthreads();
        #pragma unroll
        for (int off = 1; off < 128; off <<= 1) { __syncthreads(); __syncthreads(); }
    }
}

// ---- scan phase 3: in-block exclusive scan + block offset; re-zero g_deg ----
__global__ void k_scan3() {
    __shared__ int s[SCAN_BLK];
    int i = blockIdx.x * SCAN_BLK + threadIdx.x;
    int v = (i < N_NODES) ? g_deg[i] : 0;
    s[threadIdx.x] = v;
    __syncthreads();
    #pragma unroll
    for (int off = 1; off < SCAN_BLK; off <<= 1) {
        int u = (threadIdx.x >= off) ? s[threadIdx.x - off] : 0;
        __syncthreads();
        s[threadIdx.x] += u;
        __syncthreads();
    }
    if (i < N_NODES) {
        int excl = g_blksum[blockIdx.x] + s[threadIdx.x] - v;
        g_off[i] = excl;
        g_cur[i] = excl;
        g_deg[i] = 0;
    }
}

// ---- standalone scatter (zero smem -> full occupancy for L2 atomics) ----
__global__ void k_scatter(const int* __restrict__ src, const int* __restrict__ dst) {
    int i = blockIdx.x * blockDim.x + threadIdx.x;
    if (i * 4 >= N_EDGES) return;
    int4 s = *(const int4*)&src[i * 4];
    int4 d = *(const int4*)&dst[i * 4];
    g_srcs[atomicAdd(&g_cur[d.x], 1)] = s.x;
    g_srcs[atomicAdd(&g_cur[d.y], 1)] = s.y;
    g_srcs[atomicAdd(&g_cur[d.z], 1)] = s.z;
    g_srcs[atomicAdd(&g_cur[d.w], 1)] = s.w;
}

// ---- persistent pipelined tensor-core GEMM: 64-row tiles, 128 threads ----
// Register-prefetch pipeline: next tile's 16 LDG.128s issued before the MMA
// of the current tile, so DRAM requests stay in flight under compute.
__device__ __forceinline__ void mma16816(float* c, uint32_t a0, uint32_t a1,
                                         uint32_t a2, uint32_t a3,
                                         uint32_t b0, uint32_t b1) {
    asm volatile(
        "mma.sync.aligned.m16n8k16.row.col.f32.f16.f16.f32 "
        "{%0,%1,%2,%3}, {%4,%5,%6,%7}, {%8,%9}, {%0,%1,%2,%3};"
        : "+f"(c[0]), "+f"(c[1]), "+f"(c[2]), "+f"(c[3])
        : "r"(a0), "r"(a1), "r"(a2), "r"(a3), "r"(b0), "r"(b1));
}

__device__ __forceinline__ void prefetch_tile(const float* __restrict__ x,
                                              int tile, int t, float4* pf) {
    const int block_row = tile * 64;
    if (block_row + 64 <= N_NODES) {
        #pragma unroll
        for (int c = 0; c < 16; ++c) {
            int i = t + c * 128;
            int row = i >> 5, c4 = i & 31;
            pf[c] = *(const float4*)&x[(block_row + row) * IN_F + c4 * 4];
        }
    } else {
        #pragma unroll
        for (int c = 0; c < 16; ++c) {
            int i = t + c * 128;
            int row = i >> 5, c4 = i & 31;
            int gr = block_row + row;
            pf[c] = (gr < N_NODES) ? *(const float4*)&x[gr * IN_F + c4 * 4]
                                   : make_float4(0.f, 0.f, 0.f, 0.f);
        }
    }
}

__global__ void __launch_bounds__(128, 4) k_gemm_mma(const float* __restrict__ x) {
    __shared__ __half Xs[64][136];   // [m][k] fp16, padded rows (272B)
    __shared__ __half Wts[72][136];  // [n][k] fp16, padded rows
    const int t = threadIdx.x;       // 128 threads, 4 warps
    const int w = t >> 5, lane = t & 31;
    const int q = lane >> 2, qq = lane & 3;
    const int r0 = w * 16 + q;       // local rows r0, r0+8 (covers 64 rows)

    // W^T tile loaded once per persistent block
    for (int i = t; i < 72 * 16; i += 128) {
        int row = i >> 4, seg = i & 15;
        *(uint4*)&Wts[row][seg * 8] = *(const uint4*)&g_wt_h[row * IN_F + seg * 8];
    }

    float4 pf[16];
    int tile = blockIdx.x;
    if (tile < GEMM_TILES) prefetch_tile(x, tile, t, pf);

    for (; tile < GEMM_TILES; tile += GEMM_GRID) {
        const int block_row = tile * 64;
        __syncthreads();   // Wt ready (iter 0) / previous MMA done reading Xs
        #pragma unroll
        for (int c = 0; c < 16; ++c) {
            int i = t + c * 128;
            int row = i >> 5, c4 = i & 31;
            *(__half2*)&Xs[row][c4 * 4] = __floats2half2_rn(pf[c].x, pf[c].y);
            *(__half2*)&Xs[row][c4 * 4 + 2] = __floats2half2_rn(pf[c].z, pf[c].w);
        }
        __syncthreads();

        // kick off next tile's loads; they complete under the MMA + epilogue
        int next = tile + GEMM_GRID;
        if (next < GEMM_TILES) prefetch_tile(x, next, t, pf);

        float c[9][4];
        #pragma unroll
        for (int nt = 0; nt < 9; ++nt)
            #pragma unroll
            for (int j = 0; j < 4; ++j) c[nt][j] = 0.f;

        #pragma unroll
        for (int kt = 0; kt < 8; ++kt) {
            const int k0 = kt * 16 + qq * 2;
            uint32_t a0 = *(const uint32_t*)&Xs[r0][k0];
            uint32_t a1 = *(const uint32_t*)&Xs[r0 + 8][k0];
            uint32_t a2 = *(const uint32_t*)&Xs[r0][k0 + 8];
            uint32_t a3 = *(const uint32_t*)&Xs[r0 + 8][k0 + 8];
            #pragma unroll
            for (int nt = 0; nt < 9; ++nt) {
                uint32_t b0 = *(const uint32_t*)&Wts[nt * 8 + q][k0];
                uint32_t b1 = *(const uint32_t*)&Wts[nt * 8 + q][k0 + 8];
                mma16816(c[nt], a0, a1, a2, a3, b0, b1);
            }
        }

        // epilogue
        const int gr0 = block_row + r0;
        const int gr1 = gr0 + 8;
        #pragma unroll
        for (int nt = 0; nt < 8; ++nt) {
            int col = nt * 8 + qq * 2;
            if (gr0 < N_NODES)
                *(__half2*)&g_feat_h[gr0 * NHF + col] = __floats2half2_rn(c[nt][0], c[nt][1]);
            if (gr1 < N_NODES)
                *(__half2*)&g_feat_h[gr1 * NHF + col] = __floats2half2_rn(c[nt][2], c[nt][3]);
        }
        if (qq == 0) {          // cols 64,65 = el head0, head1
            if (gr0 < N_NODES) { g_el[gr0 * 2] = c[8][0]; g_el[gr0 * 2 + 1] = c[8][1]; }
            if (gr1 < N_NODES) { g_el[gr1 * 2] = c[8][2]; g_el[gr1 * 2 + 1] = c[8][3]; }
        } else if (qq == 1) {   // cols 66,67 = er head0, head1
            if (gr0 < N_NODES) { g_er[gr0 * 2] = c[8][0]; g_er[gr0 * 2 + 1] = c[8][1]; }
            if (gr1 < N_NODES) { g_er[gr1 * 2] = c[8][2]; g_er[gr1 * 2 + 1] = c[8][3]; }
        }
    }
}

// ---- fused per-dst-node: softmax + aggregation + epilogue (warp per node) ----
// 2 edges per inner iteration, manually unrolled x2 (4 edges, 2 gathers in
// flight) for L2-latency MLP.
__global__ void k_agg(const float* __restrict__ bias_gat) {
    int warp = (blockIdx.x * blockDim.x + threadIdx.x) >> 5;
    int lane = threadIdx.x & 31;
    if (warp >= N_NODES) return;
    const int n = warp;
    const int beg = g_off[n];
    const int end = g_off[n + 1];

    const float2 erd = *(const float2*)&g_er[n * 2];
    const int half = lane >> 4;       // which edge of the pair
    const int li = lane & 15;
    const int coff = 4 * li;          // my 4 columns
    const bool is_h0 = (li < 8);      // cols 0-31 = head0

    float4 acc = make_float4(0.f, 0.f, 0.f, 0.f);
    float den0 = 0.f, den1 = 0.f;

    for (int base = beg; base < end; base += 32) {
        const int cnt = min(32, end - base);
        int s = 0;
        float ex0 = 0.f, ex1 = 0.f;
        if (lane < cnt) {
            s = g_srcs[base + lane];
            float2 els = *(const float2*)&g_el[s * 2];
            float v0 = els.x + erd.x;
            float v1 = els.y + erd.y;
            v0 = v0 > 0.f ? v0 : 0.2f * v0;
            v1 = v1 > 0.f ? v1 : 0.2f * v1;
            ex0 = __expf(v0);
            ex1 = __expf(v1);
            den0 += ex0;             // denom accumulated once per edge here
            den1 += ex1;
        }
        const int pairs = (cnt + 1) >> 1;
        int j = 0;
        for (; j + 2 <= pairs; j += 2) {
            int idxA = 2 * j + half;
            int idxB = 2 * j + 2 + half;
            int sA = __shfl_sync(0xFFFFFFFFu, s, idxA);
            int sB = __shfl_sync(0xFFFFFFFFu, s, idxB);
            float e0A = __shfl_sync(0xFFFFFFFFu, ex0, idxA);
            float e1A = __shfl_sync(0xFFFFFFFFu, ex1, idxA);
            float e0B = __shfl_sync(0xFFFFFFFFu, ex0, idxB);
            float e1B = __shfl_sync(0xFFFFFFFFu, ex1, idxB);
            uint2 fhA = *(const uint2*)&g_feat_h[sA * NHF + coff];
            uint2 fhB = *(const uint2*)&g_feat_h[sB * NHF + coff];
            float wA = is_h0 ? e0A : e1A;
            float wB = is_h0 ? e0B : e1B;
            float2 a01 = __half22float2(*(__half2*)&fhA.x);
            float2 a23 = __half22float2(*(__half2*)&fhA.y);
            float2 b01 = __half22float2(*(__half2*)&fhB.x);
            float2 b23 = __half22float2(*(__half2*)&fhB.y);
            acc.x = fmaf(wA, a01.x, fmaf(wB, b01.x, acc.x));
            acc.y = fmaf(wA, a01.y, fmaf(wB, b01.y, acc.y));
            acc.z = fmaf(wA, a23.x, fmaf(wB, b23.x, acc.z));
            acc.w = fmaf(wA, a23.y, fmaf(wB, b23.y, acc.w));
        }
        for (; j < pairs; ++j) {
            int idx = 2 * j + half;
            int sj = __shfl_sync(0xFFFFFFFFu, s, idx);
            float e0 = __shfl_sync(0xFFFFFFFFu, ex0, idx);
            float e1 = __shfl_sync(0xFFFFFFFFu, ex1, idx);
            float wgt = is_h0 ? e0 : e1;
            uint2 fh = *(const uint2*)&g_feat_h[sj * NHF + coff];
            float2 f01 = __half22float2(*(__half2*)&fh.x);
            float2 f23 = __half22float2(*(__half2*)&fh.y);
            acc.x = fmaf(wgt, f01.x, acc.x);
            acc.y = fmaf(wgt, f01.y, acc.y);
            acc.z = fmaf(wgt, f23.x, acc.z);
            acc.w = fmaf(wgt, f23.y, acc.w);
        }
    }

    // combine the two 16-lane halves (same columns, disjoint edge subsets)
    acc.x += __shfl_xor_sync(0xFFFFFFFFu, acc.x, 16);
    acc.y += __shfl_xor_sync(0xFFFFFFFFu, acc.y, 16);
    acc.z += __shfl_xor_sync(0xFFFFFFFFu, acc.z, 16);
    acc.w += __shfl_xor_sync(0xFFFFFFFFu, acc.w, 16);
    // full-warp denom reduce
    #pragma unroll
    for (int o = 1; o < 32; o <<= 1) {
        den0 += __shfl_xor_sync(0xFFFFFFFFu, den0, o);
        den1 += __shfl_xor_sync(0xFFFFFFFFu, den1, o);
    }
    float inv0 = (den0 > 0.f) ? 1.f / den0 : 0.f;
    float inv1 = (den1 > 0.f) ? 1.f / den1 : 0.f;
    float myinv = is_h0 ? inv0 : inv1;
    float r0 = acc.x * myinv, r1 = acc.y * myinv;
    float r2 = acc.z * myinv, r3 = acc.w * myinv;
    // head swap: lane li (0-7) holds head0 f=4li..4li+3; lane li+8 head1 same f
    float o0 = __shfl_xor_sync(0xFFFFFFFFu, r0, 8);
    float o1 = __shfl_xor_sync(0xFFFFFFFFu, r1, 8);
    float o2 = __shfl_xor_sync(0xFFFFFFFFu, r2, 8);
    float o3 = __shfl_xor_sync(0xFFFFFFFFu, r3, 8);
    float4 b0 = *(const float4*)&bias_gat[coff & 31];
    float4 b1 = *(const float4*)&bias_gat[32 + (coff & 31)];
    float h0 = fmaxf(0.5f * (r0 + o0 + b0.x + b1.x), 0.f);
    float h1 = fmaxf(0.5f * (r1 + o1 + b0.y + b1.y), 0.f);
    float h2 = fmaxf(0.5f * (r2 + o2 + b0.z + b1.z), 0.f);
    float h3 = fmaxf(0.5f * (r3 + o3 + b0.w + b1.w), 0.f);
    float4 va = *(const float4*)&g_vfold[coff & 31];
    float4 vb = *(const float4*)&g_vfold[32 + (coff & 31)];
    float av = h0 * va.x + h1 * va.y + h2 * va.z + h3 * va.w;
    float bv = h0 * vb.x + h1 * vb.y + h2 * vb.z + h3 * vb.w;
    // reduce within the 8-lane group (lanes 0-7 hold the real values)
    #pragma unroll
    for (int o = 1; o < 8; o <<= 1) {
        av += __shfl_xor_sync(0xFFFFFFFFu, av, o);
        bv += __shfl_xor_sync(0xFFFFFFFFu, bv, o);
    }
    if (lane == 0) { g_a[n] = av; g_b[n] = bv; }
}

// ---- per-edge final score (4 edges per thread) ----
__global__ void k_edge_score(const int* __restrict__ src, const int* __restrict__ dst,
                             float* __restrict__ out) {
    int i = blockIdx.x * blockDim.x + threadIdx.x;
    if (i * 4 >= N_EDGES) return;
    int4 s = *(const int4*)&src[i * 4];
    int4 d = *(const int4*)&dst[i * 4];
    float c = g_cfold;
    float4 r;
    r.x = g_a[s.x] + g_b[d.x] + c;
    r.y = g_a[s.y] + g_b[d.y] + c;
    r.z = g_a[s.z] + g_b[d.z] + c;
    r.w = g_a[s.w] + g_b[d.w] + c;
    *(float4*)&out[i * 4] = r;
}

extern "C" void kernel_launch(void* const* d_in, const int* in_sizes, int n_in,
                              void* d_out, int out_size) {
    const float* x       = (const float*)d_in[0];
    const float* W       = (const float*)d_in[1];
    const float* attn_l  = (const float*)d_in[2];
    const float* attn_r  = (const float*)d_in[3];
    const float* bias_gat= (const float*)d_in[4];
    const float* W1      = (const float*)d_in[5];
    const float* b1      = (const float*)d_in[6];
    const float* W2      = (const float*)d_in[7];
    const float* b2      = (const float*)d_in[8];
    const int*   src     = (const int*)d_in[9];
    const int*   dst     = (const int*)d_in[10];
    float* out = (float*)d_out;

    k_hist<<<(N_EDGES / 4 + 255) / 256, 256>>>(dst, W, attn_l, attn_r, W1, b1, W2, b2);
    k_scan1<<<N_SCAN_BLKS, SCAN_BLK>>>();
    k_scan3<<<N_SCAN_BLKS, SCAN_BLK>>>();
    k_gemm_mma<<<GEMM_GRID, 128>>>(x);
    k_scatter<<<(N_EDGES / 4 + 255) / 256, 256>>>(src, dst);
    k_agg<<<(N_NODES * 32 + 255) / 256, 256>>>(bias_gat);
    k_edge_score<<<(N_EDGES / 4 + 255) / 256, 256>>>(src, dst, out);
}